// round 9
// baseline (speedup 1.0000x reference)
#include <cuda_runtime.h>
#include <cstdint>

// Problem constants (fixed by the dataset).
#define BB 8
#define LL 80000
#define DD 128
#define TT 200
#define NCHUNK (LL / TT)   // 400
#define CPB 4              // chunks per k1 block
#define MAXW 16

typedef unsigned long long u64;

// Per-chunk local state contributions: F[(b*NCHUNK+j)*DD + d]. 3.3 MB.
__device__ float2 d_F[BB * NCHUNK * DD];
// Per-filter params written by k1 block 0, consumed by k3.
__device__ float g_zr[DD], g_zi[DD], g_cc[DD], g_zTr[DD], g_zTi[DD];
__device__ int   g_wl[DD];

// ---------------- f32x2 packed helpers ----------------
__device__ __forceinline__ u64 pk2(float lo, float hi) {
    u64 r;
    asm("mov.b64 %0,{%1,%2};" : "=l"(r)
        : "r"(__float_as_uint(lo)), "r"(__float_as_uint(hi)));
    return r;
}
__device__ __forceinline__ float2 upk2(u64 v) {
    unsigned lo, hi;
    asm("mov.b64 {%0,%1},%2;" : "=r"(lo), "=r"(hi) : "l"(v));
    return make_float2(__uint_as_float(lo), __uint_as_float(hi));
}
__device__ __forceinline__ u64 fma2(u64 a, u64 b, u64 c) {
    u64 d;
    asm("fma.rn.f32x2 %0,%1,%2,%3;" : "=l"(d) : "l"(a), "l"(b), "l"(c));
    return d;
}
__device__ __forceinline__ u64 mul2(u64 a, u64 b) {
    u64 d;
    asm("mul.rn.f32x2 %0,%1,%2;" : "=l"(d) : "l"(a), "l"(b));
    return d;
}

// ---------------------------------------------------------------------------
// K1: params (block 0 publishes to globals) + local F for CPB chunks/block.
// Block = 64 threads; thread t owns filters (2t, 2t+1), packed f32x2.
// ---------------------------------------------------------------------------
__global__ void __launch_bounds__(64) k1_localF(
    const float* __restrict__ x,
    const float* __restrict__ omega,
    const float* __restrict__ alpha_raw,
    const float* __restrict__ b_log_mag)
{
    int blk = blockIdx.x;
    int b   = blk / (NCHUNK / CPB);
    int j0  = (blk % (NCHUNK / CPB)) * CPB;
    int t   = threadIdx.x;
    int d0  = 2 * t;

    __shared__ float2 sx[CPB * TT];
    {
        const float* xp = x + (size_t)b * LL + (size_t)j0 * TT;
        for (int i = t; i < CPB * TT; i += 64) {
            float v = xp[i];
            sx[i] = make_float2(v, v);
        }
    }

    // z, z^2..z^4 for this thread's two filters.
    float zr_s[2], zi_s[2], al_s[2];
    float z2r_s[2], z2i_s[2], z3r_s[2], z3i_s[2], z4r_s[2], z4i_s[2];
#pragma unroll
    for (int q = 0; q < 2; ++q) {
        int d = d0 + q;
        float alpha = -log1pf(expf(alpha_raw[d]));   // -softplus
        al_s[q] = alpha;
        float a = expf(alpha);
        float s1, c1; sincosf(omega[d], &s1, &c1);
        zr_s[q] = a * c1;
        zi_s[q] = a * s1;
        z2r_s[q] = fmaf(zr_s[q], zr_s[q], -zi_s[q] * zi_s[q]);
        z2i_s[q] = 2.f * zr_s[q] * zi_s[q];
        z3r_s[q] = fmaf(z2r_s[q], zr_s[q], -z2i_s[q] * zi_s[q]);
        z3i_s[q] = fmaf(z2r_s[q], zi_s[q],  z2i_s[q] * zr_s[q]);
        z4r_s[q] = fmaf(z2r_s[q], z2r_s[q], -z2i_s[q] * z2i_s[q]);
        z4i_s[q] = 2.f * z2r_s[q] * z2i_s[q];
    }
    u64 z1r  = pk2(zr_s[0],  zr_s[1]);
    u64 z1i  = pk2(zi_s[0],  zi_s[1]);
    u64 z2r  = pk2(z2r_s[0], z2r_s[1]);
    u64 z2i  = pk2(z2i_s[0], z2i_s[1]);
    u64 z3r  = pk2(z3r_s[0], z3r_s[1]);
    u64 z3i  = pk2(z3i_s[0], z3i_s[1]);
    u64 z4r  = pk2(z4r_s[0], z4r_s[1]);
    u64 z4i  = pk2(z4i_s[0], z4i_s[1]);
    u64 nz4i = pk2(-z4i_s[0], -z4i_s[1]);

    // Block 0 publishes k3's params.
    if (blk == 0) {
#pragma unroll
        for (int q = 0; q < 2; ++q) {
            int d = d0 + q;
            g_zr[d] = zr_s[q];
            g_zi[d] = zi_s[q];
            g_cc[d] = expf(2.f * b_log_mag[d]);      // |c|^2
            // z^TT: fp32 magnitude; phase reduced mod 2pi in dp.
            float aT = expf(al_s[q] * (float)TT);
            double y  = (double)omega[d] * (double)TT;
            double kq = floor(y * 0.15915494309189535);
            double r  = y - kq * 6.283185307179586;
            float s3, c3; sincosf((float)r, &s3, &c3);
            g_zTr[d] = aT * c3;
            g_zTi[d] = aT * s3;
            int wl = (int)ceilf(16.12f / (-al_s[q] * (float)TT));
            g_wl[d] = max(1, min(wl, MAXW));
        }
    }
    __syncthreads();

    // CPB independent local recurrences (4-step unrolled).
#pragma unroll
    for (int c = 0; c < CPB; ++c) {
        const u64* sxp = reinterpret_cast<const u64*>(sx + c * TT);
        u64 ar = 0ull, ai = 0ull;
#pragma unroll 5
        for (int i = 0; i < TT; i += 4) {
            u64 x0 = sxp[i], x1 = sxp[i + 1], x2 = sxp[i + 2], x3 = sxp[i + 3];
            u64 yr = fma2(z3r, x0, fma2(z2r, x1, fma2(z1r, x2, x3)));
            u64 yi = fma2(z3i, x0, fma2(z2i, x1, mul2(z1i, x2)));
            u64 nr = fma2(z4r, ar, fma2(nz4i, ai, yr));
            u64 ni = fma2(z4r, ai, fma2(z4i, ar, yi));
            ar = nr; ai = ni;
        }
        float2 fr = upk2(ar), fi = upk2(ai);
        *(float4*)&d_F[((size_t)b * NCHUNK + j0 + c) * DD + d0] =
            make_float4(fr.x, fi.x, fr.y, fi.y);
    }
}

// ---------------------------------------------------------------------------
// K3: seed via Horner over the F window (A = zT*A + F, oldest first; no
// power pair => fewer regs), then per-sample recurrence emitting cc*|A|^2.
// ---------------------------------------------------------------------------
__global__ void __launch_bounds__(64) k3_main(
    const float* __restrict__ x,
    float* __restrict__ out)
{
    int b = blockIdx.x / NCHUNK;
    int j = blockIdx.x % NCHUNK;
    int t = threadIdx.x;
    int d0 = 2 * t;

    __shared__ float2 sx[TT];
    {
        const float* xp = x + (size_t)b * LL + (size_t)j * TT;
        for (int i = t; i < TT; i += 64) {
            float v = xp[i];
            sx[i] = make_float2(v, v);
        }
    }

    // Params from globals (L2 broadcast loads, no math).
    float2 zr2  = *(const float2*)&g_zr[d0];
    float2 zi2  = *(const float2*)&g_zi[d0];
    float2 cc2  = *(const float2*)&g_cc[d0];
    float2 zTr2 = *(const float2*)&g_zTr[d0];
    float2 zTi2 = *(const float2*)&g_zTi[d0];
    int wl = max(g_wl[d0], g_wl[d0 + 1]);
    if (wl > j) wl = j;

    u64 zTr  = pk2(zTr2.x, zTr2.y);
    u64 zTi  = pk2(zTi2.x, zTi2.y);
    u64 nzTi = pk2(-zTi2.x, -zTi2.y);

    // Seed (Horner, oldest-first): A = zT (*) A + F[j-i], i = wl..1.
    u64 ar = 0ull, ai = 0ull;
    {
        const float2* Fb = d_F + (size_t)b * NCHUNK * DD;
        for (int i = wl; i >= 1; --i) {
            float4 f = *(const float4*)&Fb[(size_t)(j - i) * DD + d0];
            u64 Fr = pk2(f.x, f.z);
            u64 Fi = pk2(f.y, f.w);
            u64 nr = fma2(zTr, ar, fma2(nzTi, ai, Fr));
            u64 ni = fma2(zTr, ai, fma2(zTi, ar, Fi));
            ar = nr; ai = ni;
        }
    }

    u64 z1r  = pk2(zr2.x,  zr2.y);
    u64 z1i  = pk2(zi2.x,  zi2.y);
    u64 nz1i = pk2(-zi2.x, -zi2.y);
    u64 cc   = pk2(cc2.x,  cc2.y);

    __syncthreads();

    float* o = out + ((size_t)b * LL + (size_t)j * TT) * DD + d0;
    const u64* sxp = reinterpret_cast<const u64*>(sx);
#pragma unroll 8
    for (int u = 0; u < TT; ++u) {
        u64 xx = sxp[u];
        u64 nr = fma2(z1r, ar, fma2(nz1i, ai, xx));
        u64 ni = fma2(z1r, ai, mul2(z1i, ar));
        ar = nr; ai = ni;
        u64 pw = mul2(cc, fma2(ni, ni, mul2(nr, nr)));
        __stcs((float2*)(o + (size_t)u * DD), upk2(pw));
    }
}

// ---------------------------------------------------------------------------
// Launch. Inputs (metadata order): x, omega, alpha_raw, b_log_mag, b_phase, K.
// b_phase is provably irrelevant (power = b_mag^2 * |A|^2). K unused: the
// seed window is derived from alpha (covers >= K with tail < 1e-7).
// ---------------------------------------------------------------------------
extern "C" void kernel_launch(void* const* d_in, const int* in_sizes, int n_in,
                              void* d_out, int out_size) {
    const float* x          = (const float*)d_in[0];
    const float* omega      = (const float*)d_in[1];
    const float* alpha_raw  = (const float*)d_in[2];
    const float* b_log_mag  = (const float*)d_in[3];
    float* out = (float*)d_out;

    k1_localF<<<BB * NCHUNK / CPB, 64>>>(x, omega, alpha_raw, b_log_mag);
    k3_main<<<BB * NCHUNK, 64>>>(x, out);
}